// round 8
// baseline (speedup 1.0000x reference)
#include <cuda_runtime.h>
#include <cuda_fp16.h>

// HDBLUT 2x superresolution, GB300 sm_103a. Round 8:
//  - 1 CTA/SM x 1024 threads: single 96KB LUT copy per SM (halved fill)
//  - LUT float4->half4 conversion folded into the smem fill (no g_lut)
//  - prelude packs image only (row/block int4 packer)
//  - row-pair core identical to R7 (gather-conflict floor ~39us)

#define NN 2048
#define NTILES (1024 * 64)        // row-pairs x 32-col tiles
#define THREADS 1024
#define WARPS_PER_CTA (THREADS / 32)
#define LUT_E (3 * 4096)
#define PSTRIDE 260
#define PWORDS 257
#define SMEM_BYTES (LUT_E * 8)

__device__ unsigned g_pimg[NN * PSTRIDE];      // nibble-packed image

__device__ __forceinline__ int refl(int t) {
    t = (t < 0) ? -t : t;
    return (t >= NN) ? (2 * NN - 2 - t) : t;
}

__device__ __forceinline__ __half2 u2h(unsigned u) {
    return *reinterpret_cast<__half2*>(&u);
}

// One block per image row: int4 loads staged through smem, nibble-pack with
// reflection baked in.
__global__ void hdblut_pack(const int* __restrict__ img)
{
    __shared__ int srow[2056];
    const int tid = threadIdx.x;
    const int r = blockIdx.x;

    const int4* row4 = reinterpret_cast<const int4*>(img + (size_t)r * NN);
    #pragma unroll
    for (int k = 0; k < 2; k++) {
        int i = tid + k * 256;
        int4 v = __ldg(row4 + i);
        srow[2 + i * 4 + 0] = v.x;
        srow[2 + i * 4 + 1] = v.y;
        srow[2 + i * 4 + 2] = v.z;
        srow[2 + i * 4 + 3] = v.w;
    }
    __syncthreads();
    if (tid == 0) {
        srow[0] = srow[4];
        srow[1] = srow[3];
        #pragma unroll
        for (int i = 0; i < 6; i++)
            srow[2050 + i] = srow[2048 - i];
    }
    __syncthreads();
    for (int wi = tid; wi < PWORDS; wi += 256) {
        const int* s = srow + wi * 8;
        unsigned val = 0;
        #pragma unroll
        for (int j = 0; j < 8; j++)
            val |= (unsigned)(s[j] & 15) << (4 * j);
        g_pimg[(size_t)r * PSTRIDE + wi] = val;
    }
}

__global__ __launch_bounds__(THREADS, 1)
void hdblut_main(const float4* __restrict__ wlut, float2* __restrict__ out)
{
    extern __shared__ uint2 slut[];   // 96 KB fp16 LUT (1/3 scale folded)

    // Fill smem LUT straight from gmem float4, converting in-register.
    for (int i = threadIdx.x; i < LUT_E; i += THREADS) {
        float4 v = __ldg(wlut + i);
        const float s = 1.0f / 3.0f;
        __half2 lo = __floats2half2_rn(v.x * s, v.y * s);
        __half2 hi = __floats2half2_rn(v.z * s, v.w * s);
        uint2 u;
        u.x = *reinterpret_cast<unsigned*>(&lo);
        u.y = *reinterpret_cast<unsigned*>(&hi);
        slut[i] = u;
    }
    __syncthreads();

    const int warp = threadIdx.x >> 5;
    const int lane = threadIdx.x & 31;
    const int gwarp  = blockIdx.x * WARPS_PER_CTA + warp;
    const int nwarps = gridDim.x * WARPS_PER_CTA;

    for (int t = gwarp; t < NTILES; t += nwarps) {
        const int I  = (t >> 6) << 1;       // low-res row pair (I, I+1)
        const int Jb = (t & 63) << 5;

        // 6 packed rows I-2..I+3; nibble j of rc[i] = img col J-2+j (J=Jb+lane)
        unsigned rc[6];
        {
            const int pos = Jb + lane;
            const int wi  = pos >> 3;
            const int sh  = (pos & 7) * 4;
            #pragma unroll
            for (int i = 0; i < 6; i++) {
                const unsigned* pr = g_pimg + (size_t)refl(I - 2 + i) * PSTRIDE + wi;
                unsigned w0 = __ldg(pr);
                unsigned w1 = __ldg(pr + 1);
                rc[i] = __funnelshift_r(w0, w1, sh);
            }
        }

        float acc[2][4];
        #pragma unroll
        for (int ro = 0; ro < 2; ro++)
            acc[ro][0] = acc[ro][1] = acc[ro][2] = acc[ro][3] = 0.f;

        #define NIB(i, j)  ((int)((rc[(i)] >> (4 * (j))) & 15u))
        #define GIDX(ro, k, bx, by, cx, cy) \
            ((k) * 4096 + a8 + (NIB(2 + (ro) + (bx), 2 + (by)) << 4) \
                            +  NIB(2 + (ro) + (cx), 2 + (cy)))

        // One rotation = 3 gathers (k=0,1,2) sharing a permutation:
        //   r=0: (0,1,2,3)  r=1: (2,0,3,1)  r=2: (3,2,1,0)  r=3: (1,3,0,2)
        #define ROT3(ro, b0x,b0y,c0x,c0y, b1x,b1y,c1x,c1y, b2x,b2y,c2x,c2y, \
                     i00,i01,i10,i11) do {                                  \
            uint2 h0 = slut[GIDX(ro, 0, b0x,b0y, c0x,c0y)];                 \
            uint2 h1 = slut[GIDX(ro, 1, b1x,b1y, c1x,c1y)];                 \
            uint2 h2 = slut[GIDX(ro, 2, b2x,b2y, c2x,c2y)];                 \
            __half2 sA = __hadd2(__hadd2(u2h(h0.x), u2h(h1.x)), u2h(h2.x)); \
            __half2 sB = __hadd2(__hadd2(u2h(h0.y), u2h(h1.y)), u2h(h2.y)); \
            float2 fA = __half22float2(sA);                                 \
            float2 fB = __half22float2(sB);                                 \
            float fv[4] = {fA.x, fA.y, fB.x, fB.y};                         \
            acc[ro][0] += fv[i00]; acc[ro][1] += fv[i01];                   \
            acc[ro][2] += fv[i10]; acc[ro][3] += fv[i11];                   \
        } while (0)

        #pragma unroll
        for (int ro = 0; ro < 2; ro++) {
            const int a8 = NIB(2 + ro, 2) << 8;
            // r = 0: offsets as-is
            ROT3(ro,  0, 1,  0, 2,   1, 1,  2, 2,   1, 2,  2, 1,  0,1,2,3);
            // r = 1: (x,y) -> (y,-x)
            ROT3(ro,  1, 0,  2, 0,   1,-1,  2,-2,   2,-1,  1,-2,  2,0,3,1);
            // r = 2: (x,y) -> (-x,-y)
            ROT3(ro,  0,-1,  0,-2,  -1,-1, -2,-2,  -1,-2, -2,-1,  3,2,1,0);
            // r = 3: (x,y) -> (-y,x)
            ROT3(ro, -1, 0, -2, 0,  -1, 1, -2, 2,  -2, 1, -1, 2,  1,3,0,2);
        }

        #undef ROT3
        #undef GIDX
        #undef NIB

        const int J = Jb + lane;
        const size_t base = (size_t)(2 * I) * 2048 + J;
        out[base        ] = make_float2(acc[0][0], acc[0][1]);
        out[base + 2048 ] = make_float2(acc[0][2], acc[0][3]);
        out[base + 4096 ] = make_float2(acc[1][0], acc[1][1]);
        out[base + 6144 ] = make_float2(acc[1][2], acc[1][3]);
    }
}

extern "C" void kernel_launch(void* const* d_in, const int* in_sizes, int n_in,
                              void* d_out, int out_size)
{
    const int*    img  = (const int*)d_in[0];
    const float4* wlut = (const float4*)d_in[1];
    float2*       out  = (float2*)d_out;

    int sms = 0;
    cudaDeviceGetAttribute(&sms, cudaDevAttrMultiProcessorCount, 0);
    if (sms <= 0) sms = 148;

    hdblut_pack<<<NN, 256>>>(img);

    cudaFuncSetAttribute(hdblut_main,
                         cudaFuncAttributeMaxDynamicSharedMemorySize, SMEM_BYTES);
    hdblut_main<<<sms, THREADS, SMEM_BYTES>>>(wlut, out);
}

// round 9
// speedup vs baseline: 1.0388x; 1.0388x over previous
#include <cuda_runtime.h>
#include <cuda_fp16.h>

// HDBLUT 2x superresolution, GB300 sm_103a. Round 9:
//  - row-pair core at 2 CTAs x 768 thr = 48 warps/SM (reg target <=42:
//    pixels processed serially, stores issued mid-loop to free accumulators)
//  - LUT float4->half4 conversion folded into smem fill
//  - image nibble-pack prelude (row/block int4 packer)

#define NN 2048
#define NTILES (1024 * 64)        // row-pairs x 32-col tiles
#define THREADS 768
#define WARPS_PER_CTA (THREADS / 32)
#define LUT_E (3 * 4096)
#define PSTRIDE 260
#define PWORDS 257
#define SMEM_BYTES (LUT_E * 8)

__device__ unsigned g_pimg[NN * PSTRIDE];      // nibble-packed image

__device__ __forceinline__ int refl(int t) {
    t = (t < 0) ? -t : t;
    return (t >= NN) ? (2 * NN - 2 - t) : t;
}

__device__ __forceinline__ __half2 u2h(unsigned u) {
    return *reinterpret_cast<__half2*>(&u);
}

// One block per image row: int4 loads staged through smem, nibble-pack with
// reflection baked in.
__global__ void hdblut_pack(const int* __restrict__ img)
{
    __shared__ int srow[2056];
    const int tid = threadIdx.x;
    const int r = blockIdx.x;

    const int4* row4 = reinterpret_cast<const int4*>(img + (size_t)r * NN);
    #pragma unroll
    for (int k = 0; k < 2; k++) {
        int i = tid + k * 256;
        int4 v = __ldg(row4 + i);
        srow[2 + i * 4 + 0] = v.x;
        srow[2 + i * 4 + 1] = v.y;
        srow[2 + i * 4 + 2] = v.z;
        srow[2 + i * 4 + 3] = v.w;
    }
    __syncthreads();
    if (tid == 0) {
        srow[0] = srow[4];
        srow[1] = srow[3];
        #pragma unroll
        for (int i = 0; i < 6; i++)
            srow[2050 + i] = srow[2048 - i];
    }
    __syncthreads();
    for (int wi = tid; wi < PWORDS; wi += 256) {
        const int* s = srow + wi * 8;
        unsigned val = 0;
        #pragma unroll
        for (int j = 0; j < 8; j++)
            val |= (unsigned)(s[j] & 15) << (4 * j);
        g_pimg[(size_t)r * PSTRIDE + wi] = val;
    }
}

__global__ __launch_bounds__(THREADS, 2)
void hdblut_main(const float4* __restrict__ wlut, float2* __restrict__ out)
{
    extern __shared__ uint2 slut[];   // 96 KB fp16 LUT (1/3 scale folded)

    for (int i = threadIdx.x; i < LUT_E; i += THREADS) {
        float4 v = __ldg(wlut + i);
        const float s = 1.0f / 3.0f;
        __half2 lo = __floats2half2_rn(v.x * s, v.y * s);
        __half2 hi = __floats2half2_rn(v.z * s, v.w * s);
        uint2 u;
        u.x = *reinterpret_cast<unsigned*>(&lo);
        u.y = *reinterpret_cast<unsigned*>(&hi);
        slut[i] = u;
    }
    __syncthreads();

    const int warp = threadIdx.x >> 5;
    const int lane = threadIdx.x & 31;
    const int gwarp  = blockIdx.x * WARPS_PER_CTA + warp;
    const int nwarps = gridDim.x * WARPS_PER_CTA;

    for (int t = gwarp; t < NTILES; t += nwarps) {
        const int I  = (t >> 6) << 1;       // low-res row pair (I, I+1)
        const int Jb = (t & 63) << 5;

        // 6 packed rows I-2..I+3; nibble j of rc[i] = img col J-2+j (J=Jb+lane)
        unsigned rc[6];
        {
            const int pos = Jb + lane;
            const int wi  = pos >> 3;
            const int sh  = (pos & 7) * 4;
            #pragma unroll
            for (int i = 0; i < 6; i++) {
                const unsigned* pr = g_pimg + (size_t)refl(I - 2 + i) * PSTRIDE + wi;
                unsigned w0 = __ldg(pr);
                unsigned w1 = __ldg(pr + 1);
                rc[i] = __funnelshift_r(w0, w1, sh);
            }
        }

        const int J = Jb + lane;
        const size_t obase = (size_t)(2 * I) * 2048 + J;

        #define NIB(i, j)  ((int)((rc[(i)] >> (4 * (j))) & 15u))
        #define GIDX(ro, k, bx, by, cx, cy) \
            ((k) * 4096 + a8 + (NIB(2 + (ro) + (bx), 2 + (by)) << 4) \
                            +  NIB(2 + (ro) + (cx), 2 + (cy)))

        #define ROT3(ro, b0x,b0y,c0x,c0y, b1x,b1y,c1x,c1y, b2x,b2y,c2x,c2y, \
                     i00,i01,i10,i11) do {                                  \
            uint2 h0 = slut[GIDX(ro, 0, b0x,b0y, c0x,c0y)];                 \
            uint2 h1 = slut[GIDX(ro, 1, b1x,b1y, c1x,c1y)];                 \
            uint2 h2 = slut[GIDX(ro, 2, b2x,b2y, c2x,c2y)];                 \
            __half2 sA = __hadd2(__hadd2(u2h(h0.x), u2h(h1.x)), u2h(h2.x)); \
            __half2 sB = __hadd2(__hadd2(u2h(h0.y), u2h(h1.y)), u2h(h2.y)); \
            float2 fA = __half22float2(sA);                                 \
            float2 fB = __half22float2(sB);                                 \
            float fv[4] = {fA.x, fA.y, fB.x, fB.y};                         \
            o00 += fv[i00]; o01 += fv[i01];                                 \
            o10 += fv[i10]; o11 += fv[i11];                                 \
        } while (0)

        // Pixels processed serially to keep live registers low.
        #pragma unroll
        for (int ro = 0; ro < 2; ro++) {
            const int a8 = NIB(2 + ro, 2) << 8;
            float o00 = 0.f, o01 = 0.f, o10 = 0.f, o11 = 0.f;

            // r = 0: offsets as-is       perm (0,1,2,3)
            ROT3(ro,  0, 1,  0, 2,   1, 1,  2, 2,   1, 2,  2, 1,  0,1,2,3);
            // r = 1: (x,y)->(y,-x)       perm (2,0,3,1)
            ROT3(ro,  1, 0,  2, 0,   1,-1,  2,-2,   2,-1,  1,-2,  2,0,3,1);
            // r = 2: (x,y)->(-x,-y)      perm (3,2,1,0)
            ROT3(ro,  0,-1,  0,-2,  -1,-1, -2,-2,  -1,-2, -2,-1,  3,2,1,0);
            // r = 3: (x,y)->(-y,x)       perm (1,3,0,2)
            ROT3(ro, -1, 0, -2, 0,  -1, 1, -2, 2,  -2, 1, -1, 2,  1,3,0,2);

            out[obase + (size_t)(2 * ro)     * 2048] = make_float2(o00, o01);
            out[obase + (size_t)(2 * ro + 1) * 2048] = make_float2(o10, o11);
        }

        #undef ROT3
        #undef GIDX
        #undef NIB
    }
}

extern "C" void kernel_launch(void* const* d_in, const int* in_sizes, int n_in,
                              void* d_out, int out_size)
{
    const int*    img  = (const int*)d_in[0];
    const float4* wlut = (const float4*)d_in[1];
    float2*       out  = (float2*)d_out;

    int sms = 0;
    cudaDeviceGetAttribute(&sms, cudaDevAttrMultiProcessorCount, 0);
    if (sms <= 0) sms = 148;

    hdblut_pack<<<NN, 256>>>(img);

    cudaFuncSetAttribute(hdblut_main,
                         cudaFuncAttributeMaxDynamicSharedMemorySize, SMEM_BYTES);
    hdblut_main<<<2 * sms, THREADS, SMEM_BYTES>>>(wlut, out);
}